// round 5
// baseline (speedup 1.0000x reference)
#include <cuda_runtime.h>

#define HH 64
#define WW 64
#define HWN 4096
#define BB 32
#define CC 256
#define CPB 8   // channels per block in dot kernel

// Scratch: accumulated weight map A[b][h][w] (already scaled by 1/HW)
__device__ float g_A[BB * HWN];

// One block per batch: zero SMEM plane, scatter all 4096 pixels' bilinear
// weights into it, write the finished plane to g_A with plain vector stores.
// No zero kernel, no global atomics.
__global__ void __launch_bounds__(256) scatter_kernel(
    const float* __restrict__ offset, const float* __restrict__ ts_ptr)
{
    int b = blockIdx.x;

    __shared__ float sA[HWN];
    for (int i = threadIdx.x; i < HWN; i += 256) sA[i] = 0.0f;
    __syncthreads();

    float ts = fminf(fmaxf(ts_ptr[0], 0.001f), 0.01f);
    const float inv = 1.0f / (float)HWN;
    const float* offy = offset + (size_t)b * 2 * HWN;
    const float* offx = offy + HWN;

#pragma unroll
    for (int k = 0; k < 16; ++k) {
        int p = k * 256 + threadIdx.x;
        int i = p >> 6;
        int j = p & 63;
        float y = fminf(fmaxf((float)i + ts * offy[p] * 64.0f, 0.0f), 63.0f);
        float x = fminf(fmaxf((float)j + ts * offx[p] * 64.0f, 0.0f), 63.0f);
        int y0 = (int)floorf(y); if (y0 > 62) y0 = 62;
        int x0 = (int)floorf(x); if (x0 > 62) x0 = 62;
        float wy = y - (float)y0;
        float wx = x - (float)x0;
        float w00 = (1.0f - wy) * (1.0f - wx);
        float w01 = (1.0f - wy) * wx;
        float w10 = wy * (1.0f - wx);
        float w11 = wy * wx;
        int base = (y0 << 6) + x0;
        atomicAdd(&sA[base],          w00 * inv);
        atomicAdd(&sA[base + 1],      w01 * inv);
        atomicAdd(&sA[base + WW],     w10 * inv);
        atomicAdd(&sA[base + WW + 1], w11 * inv);
    }
    __syncthreads();

    float4* Ab = (float4*)(g_A + (size_t)b * HWN);
    const float4* s4 = (const float4*)sA;
    for (int i = threadIdx.x; i < HWN / 4; i += 256) Ab[i] = s4[i];
}

// out[b,c] = dot(A[b], data[b,c]).
// Each thread needs only A4[tid + k*256] (k=0..3) — identical indices for all
// channels — so A lives in 4 float4 registers (L2-cached, 32x reuse per batch).
// Mainloop is pure streaming LDG.128 of data + FFMA. No smem staging, no sync.
__global__ void __launch_bounds__(256) dot_kernel(
    const float* __restrict__ data, float* __restrict__ out)
{
    int b  = blockIdx.x >> 5;   // CC/CPB = 32 channel-groups per batch
    int cg = blockIdx.x & 31;

    const float4* A4 = (const float4*)(g_A + (size_t)b * HWN);
    float4 av[4];
#pragma unroll
    for (int k = 0; k < 4; ++k) av[k] = __ldg(&A4[threadIdx.x + k * 256]);

    const float4* dp = (const float4*)(data + ((size_t)b * CC + (size_t)cg * CPB) * HWN);

    float acc[CPB];
#pragma unroll
    for (int ch = 0; ch < CPB; ++ch) acc[ch] = 0.0f;

#pragma unroll
    for (int ch = 0; ch < CPB; ++ch) {
        const float4* d4 = dp + ch * (HWN / 4);
#pragma unroll
        for (int k = 0; k < 4; ++k) {
            float4 dv = __ldg(&d4[threadIdx.x + k * 256]);
            acc[ch] += dv.x * av[k].x + dv.y * av[k].y
                     + dv.z * av[k].z + dv.w * av[k].w;
        }
    }

    int lane = threadIdx.x & 31;
    int warp = threadIdx.x >> 5;
    __shared__ float red[8][CPB];
#pragma unroll
    for (int ch = 0; ch < CPB; ++ch) {
        float v = acc[ch];
#pragma unroll
        for (int o = 16; o > 0; o >>= 1) v += __shfl_down_sync(0xffffffffu, v, o);
        if (lane == 0) red[warp][ch] = v;
    }
    __syncthreads();

    if (threadIdx.x < CPB) {
        float s = 0.0f;
#pragma unroll
        for (int w = 0; w < 8; ++w) s += red[w][threadIdx.x];
        out[b * CC + cg * CPB + threadIdx.x] = s;
    }
}

extern "C" void kernel_launch(void* const* d_in, const int* in_sizes, int n_in,
                              void* d_out, int out_size)
{
    const float* data   = (const float*)d_in[0];   // [32,256,64,64]
    const float* offset = (const float*)d_in[1];   // [32,2,64,64]
    const float* ts     = (const float*)d_in[2];   // scalar
    float* out = (float*)d_out;                    // [32,256]

    scatter_kernel<<<BB, 256>>>(offset, ts);
    dot_kernel<<<BB * (CC / CPB), 256>>>(data, out);
}

// round 6
// speedup vs baseline: 1.3536x; 1.3536x over previous
#include <cuda_runtime.h>

#define HH 64
#define WW 64
#define HWN 4096
#define BB 32
#define CC 256
#define CPB 8       // channels per block in dot kernel
#define NCHUNK 4    // scatter partial slabs

// Partial weight maps: g_part[chunk][b][h*W+w], summed by the dot kernel.
// Plain stores only — no zero kernel, no global atomics.
__device__ float g_part[NCHUNK][BB * HWN];

// grid = (NCHUNK, BB), 256 threads. Each block scatters 1024 pixels' bilinear
// weights into a private SMEM plane, then vector-stores the whole plane into
// its own partial slab.
__global__ void __launch_bounds__(256) scatter_kernel(
    const float* __restrict__ offset, const float* __restrict__ ts_ptr)
{
    int chunk = blockIdx.x;
    int b = blockIdx.y;

    __shared__ float sA[HWN];
    for (int i = threadIdx.x; i < HWN; i += 256) sA[i] = 0.0f;
    __syncthreads();

    float ts = fminf(fmaxf(ts_ptr[0], 0.001f), 0.01f);
    const float inv = 1.0f / (float)HWN;
    const float* offy = offset + (size_t)b * 2 * HWN;
    const float* offx = offy + HWN;

#pragma unroll
    for (int k = 0; k < 4; ++k) {
        int p = chunk * 1024 + k * 256 + threadIdx.x;
        int i = p >> 6;
        int j = p & 63;
        float y = fminf(fmaxf((float)i + ts * offy[p] * 64.0f, 0.0f), 63.0f);
        float x = fminf(fmaxf((float)j + ts * offx[p] * 64.0f, 0.0f), 63.0f);
        int y0 = (int)floorf(y); if (y0 > 62) y0 = 62;
        int x0 = (int)floorf(x); if (x0 > 62) x0 = 62;
        float wy = y - (float)y0;
        float wx = x - (float)x0;
        float w00 = (1.0f - wy) * (1.0f - wx);
        float w01 = (1.0f - wy) * wx;
        float w10 = wy * (1.0f - wx);
        float w11 = wy * wx;
        int base = (y0 << 6) + x0;
        atomicAdd(&sA[base],          w00 * inv);
        atomicAdd(&sA[base + 1],      w01 * inv);
        atomicAdd(&sA[base + WW],     w10 * inv);
        atomicAdd(&sA[base + WW + 1], w11 * inv);
    }
    __syncthreads();

    float4* Pb = (float4*)(g_part[chunk] + (size_t)b * HWN);
    const float4* s4 = (const float4*)sA;
    for (int i = threadIdx.x; i < HWN / 4; i += 256) Pb[i] = s4[i];
}

// out[b,c] = dot(A[b], data[b,c]), A[b] = sum of 4 partial slabs (L2 hits).
// k-outer / channel-inner: 8 independent LDG.128 per k step (high MLP), all
// sharing one register-held av[k]. Pure streaming HBM + FFMA.
__global__ void __launch_bounds__(256) dot_kernel(
    const float* __restrict__ data, float* __restrict__ out)
{
    int b  = blockIdx.x >> 5;   // CC/CPB = 32 channel-groups per batch
    int cg = blockIdx.x & 31;

    // Build A in registers: sum the 4 partial planes at this thread's offsets.
    float4 av[4];
#pragma unroll
    for (int k = 0; k < 4; ++k) {
        int idx = (b << 10) + threadIdx.x + k * 256;   // b*HWN/4 + ...
        float4 a = __ldg((const float4*)g_part[0] + idx);
#pragma unroll
        for (int c = 1; c < NCHUNK; ++c) {
            float4 p = __ldg((const float4*)g_part[c] + idx);
            a.x += p.x; a.y += p.y; a.z += p.z; a.w += p.w;
        }
        av[k] = a;
    }

    const float4* dp = (const float4*)(data + ((size_t)b * CC + (size_t)cg * CPB) * HWN);

    float acc[CPB];
#pragma unroll
    for (int ch = 0; ch < CPB; ++ch) acc[ch] = 0.0f;

#pragma unroll
    for (int k = 0; k < 4; ++k) {
        int idx = threadIdx.x + k * 256;
        float4 dv[CPB];
#pragma unroll
        for (int ch = 0; ch < CPB; ++ch)
            dv[ch] = __ldg(dp + ch * (HWN / 4) + idx);
#pragma unroll
        for (int ch = 0; ch < CPB; ++ch)
            acc[ch] += dv[ch].x * av[k].x + dv[ch].y * av[k].y
                     + dv[ch].z * av[k].z + dv[ch].w * av[k].w;
    }

    int lane = threadIdx.x & 31;
    int warp = threadIdx.x >> 5;
    __shared__ float red[8][CPB];
#pragma unroll
    for (int ch = 0; ch < CPB; ++ch) {
        float v = acc[ch];
#pragma unroll
        for (int o = 16; o > 0; o >>= 1) v += __shfl_down_sync(0xffffffffu, v, o);
        if (lane == 0) red[warp][ch] = v;
    }
    __syncthreads();

    if (threadIdx.x < CPB) {
        float s = 0.0f;
#pragma unroll
        for (int w = 0; w < 8; ++w) s += red[w][threadIdx.x];
        out[b * CC + cg * CPB + threadIdx.x] = s;
    }
}

extern "C" void kernel_launch(void* const* d_in, const int* in_sizes, int n_in,
                              void* d_out, int out_size)
{
    const float* data   = (const float*)d_in[0];   // [32,256,64,64]
    const float* offset = (const float*)d_in[1];   // [32,2,64,64]
    const float* ts     = (const float*)d_in[2];   // scalar
    float* out = (float*)d_out;                    // [32,256]

    scatter_kernel<<<dim3(NCHUNK, BB), 256>>>(offset, ts);
    dot_kernel<<<BB * (CC / CPB), 256>>>(data, out);
}

// round 7
// speedup vs baseline: 1.4537x; 1.0740x over previous
#include <cuda_runtime.h>

#define HH 64
#define WW 64
#define HWN 4096
#define BB 32
#define CC 256
#define CPB 16      // channels per block in dot kernel
#define NCHUNK 4    // scatter partial slabs

// Partial weight maps: g_part[chunk][b][h*W+w], summed by the dot kernel.
// Plain stores only — no zero kernel, no global atomics.
__device__ float g_part[NCHUNK][BB * HWN];

// grid = (NCHUNK, BB), 256 threads. Each block scatters 1024 pixels' bilinear
// weights into a private SMEM plane, then vector-stores the whole plane into
// its own partial slab.
__global__ void __launch_bounds__(256) scatter_kernel(
    const float* __restrict__ offset, const float* __restrict__ ts_ptr)
{
    int chunk = blockIdx.x;
    int b = blockIdx.y;

    __shared__ float sA[HWN];
    for (int i = threadIdx.x; i < HWN; i += 256) sA[i] = 0.0f;
    __syncthreads();

    float ts = fminf(fmaxf(ts_ptr[0], 0.001f), 0.01f);
    const float inv = 1.0f / (float)HWN;
    const float* offy = offset + (size_t)b * 2 * HWN;
    const float* offx = offy + HWN;

#pragma unroll
    for (int k = 0; k < 4; ++k) {
        int p = chunk * 1024 + k * 256 + threadIdx.x;
        int i = p >> 6;
        int j = p & 63;
        float y = fminf(fmaxf((float)i + ts * offy[p] * 64.0f, 0.0f), 63.0f);
        float x = fminf(fmaxf((float)j + ts * offx[p] * 64.0f, 0.0f), 63.0f);
        int y0 = (int)floorf(y); if (y0 > 62) y0 = 62;
        int x0 = (int)floorf(x); if (x0 > 62) x0 = 62;
        float wy = y - (float)y0;
        float wx = x - (float)x0;
        float w00 = (1.0f - wy) * (1.0f - wx);
        float w01 = (1.0f - wy) * wx;
        float w10 = wy * (1.0f - wx);
        float w11 = wy * wx;
        int base = (y0 << 6) + x0;
        atomicAdd(&sA[base],          w00 * inv);
        atomicAdd(&sA[base + 1],      w01 * inv);
        atomicAdd(&sA[base + WW],     w10 * inv);
        atomicAdd(&sA[base + WW + 1], w11 * inv);
    }
    __syncthreads();

    float4* Pb = (float4*)(g_part[chunk] + (size_t)b * HWN);
    const float4* s4 = (const float4*)sA;
    for (int i = threadIdx.x; i < HWN / 4; i += 256) Pb[i] = s4[i];
}

// out[b,c] = dot(A[b], data[b,c]), A[b] = sum of 4 partial slabs (L2 hits).
// CPB=16, grid = 32*16 = 512 blocks; with <=64 regs and 4 blocks/SM the whole
// grid is a SINGLE WAVE (592 slots) — no tail, no wave transition.
// k-outer / 4-channel inner batches: MLP 4 streaming LDG.128 + FFMA against
// register-held av[k].
__global__ void __launch_bounds__(256, 4) dot_kernel(
    const float* __restrict__ data, float* __restrict__ out)
{
    int b  = blockIdx.x >> 4;   // CC/CPB = 16 channel-groups per batch
    int cg = blockIdx.x & 15;

    // Build A in registers: sum the 4 partial planes at this thread's offsets.
    float4 av[4];
#pragma unroll
    for (int k = 0; k < 4; ++k) {
        int idx = (b << 10) + threadIdx.x + k * 256;   // b*HWN/4 + ...
        float4 a = __ldg((const float4*)g_part[0] + idx);
#pragma unroll
        for (int c = 1; c < NCHUNK; ++c) {
            float4 p = __ldg((const float4*)g_part[c] + idx);
            a.x += p.x; a.y += p.y; a.z += p.z; a.w += p.w;
        }
        av[k] = a;
    }

    const float4* dp = (const float4*)(data + ((size_t)b * CC + (size_t)cg * CPB) * HWN);

    float acc[CPB];
#pragma unroll
    for (int ch = 0; ch < CPB; ++ch) acc[ch] = 0.0f;

#pragma unroll
    for (int k = 0; k < 4; ++k) {
        int idx = threadIdx.x + k * 256;
#pragma unroll
        for (int chb = 0; chb < CPB / 4; ++chb) {
            float4 dv[4];
#pragma unroll
            for (int c = 0; c < 4; ++c)
                dv[c] = __ldg(dp + (chb * 4 + c) * (HWN / 4) + idx);
#pragma unroll
            for (int c = 0; c < 4; ++c)
                acc[chb * 4 + c] += dv[c].x * av[k].x + dv[c].y * av[k].y
                                  + dv[c].z * av[k].z + dv[c].w * av[k].w;
        }
    }

    int lane = threadIdx.x & 31;
    int warp = threadIdx.x >> 5;
    __shared__ float red[8][CPB];
#pragma unroll
    for (int ch = 0; ch < CPB; ++ch) {
        float v = acc[ch];
#pragma unroll
        for (int o = 16; o > 0; o >>= 1) v += __shfl_down_sync(0xffffffffu, v, o);
        if (lane == 0) red[warp][ch] = v;
    }
    __syncthreads();

    if (threadIdx.x < CPB) {
        float s = 0.0f;
#pragma unroll
        for (int w = 0; w < 8; ++w) s += red[w][threadIdx.x];
        out[b * CC + cg * CPB + threadIdx.x] = s;
    }
}

extern "C" void kernel_launch(void* const* d_in, const int* in_sizes, int n_in,
                              void* d_out, int out_size)
{
    const float* data   = (const float*)d_in[0];   // [32,256,64,64]
    const float* offset = (const float*)d_in[1];   // [32,2,64,64]
    const float* ts     = (const float*)d_in[2];   // scalar
    float* out = (float*)d_out;                    // [32,256]

    scatter_kernel<<<dim3(NCHUNK, BB), 256>>>(offset, ts);
    dot_kernel<<<BB * (CC / CPB), 256>>>(data, out);
}